// round 15
// baseline (speedup 1.0000x reference)
#include <cuda_runtime.h>
#include <cuda_bf16.h>

#define NN 50000
#define EE 1600000
#define GG 64
#define F_IN 24
#define DD 64
#define HH 4
#define CC 16
#define LL 3
#define NEG 0.2f
#define LN_EPS 1e-5f

#define SCAN_B 1024
#define NB ((NN + SCAN_B - 1) / SCAN_B)   // 49
#define COLCAP (EE + 8 * NN)              // padded CSR capacity (pad to mult of 8)

// ---------------- device scratch (static, no allocation) ----------------
__device__ float        g_h[NN * DD];
__device__ unsigned int g_xlb[(NN + 1) * 32];   // xl as bf16x2: 128B/row -> 1 line/edge gather
__device__ float        g_xr[NN * DD];
__device__ int   g_deg[NN];
__device__ int   g_excl[NN];
__device__ int   g_row[NN + 1];         // padded offsets; g_row[NN] = total
__device__ int   g_cur[NN];             // fill cursor; after fill = beg+deg
__device__ int   g_col[COLCAP];
__device__ int   g_bsum[NB];
__device__ float g_gate[NN];
__device__ int   g_gstart[GG];
__device__ int   g_gend[GG];

// ---------------- helpers ----------------
__device__ __forceinline__ float grp8_sum(float p) {
    p += __shfl_xor_sync(0xffffffffu, p, 1);
    p += __shfl_xor_sync(0xffffffffu, p, 2);
    p += __shfl_xor_sync(0xffffffffu, p, 4);
    return p;
}
__device__ __forceinline__ float warp_sum(float s) {
#pragma unroll
    for (int o = 16; o; o >>= 1) s += __shfl_xor_sync(0xffffffffu, s, o);
    return s;
}

// ---- packed f32x2 ops (only reachable via PTX on sm_103a) ----
typedef unsigned long long u64t;
__device__ __forceinline__ u64t pack2(float x, float y) {
    u64t r; asm("mov.b64 %0,{%1,%2};" : "=l"(r) : "f"(x), "f"(y)); return r;
}
__device__ __forceinline__ u64t packb(float x) {
    u64t r; asm("mov.b64 %0,{%1,%1};" : "=l"(r) : "f"(x)); return r;
}
__device__ __forceinline__ u64t fma2(u64t a, u64t b, u64t c) {
    u64t d; asm("fma.rn.f32x2 %0,%1,%2,%3;" : "=l"(d) : "l"(a), "l"(b), "l"(c)); return d;
}
__device__ __forceinline__ u64t add2(u64t a, u64t b) {
    u64t d; asm("add.rn.f32x2 %0,%1,%2;" : "=l"(d) : "l"(a), "l"(b)); return d;
}
__device__ __forceinline__ u64t mul2(u64t a, u64t b) {
    u64t d; asm("mul.rn.f32x2 %0,%1,%2;" : "=l"(d) : "l"(a), "l"(b)); return d;
}
__device__ __forceinline__ float2 unpack2(u64t v) {
    float2 f; asm("mov.b64 {%0,%1},%2;" : "=f"(f.x), "=f"(f.y) : "l"(v)); return f;
}
__device__ __forceinline__ float ex2(float x) {
    float y; asm("ex2.approx.f32 %0,%1;" : "=f"(y) : "f"(x)); return y;
}
// bf16x2 (u32) -> packed f32x2 (u64): 2 ALU ops (SHF+LOP3) + free reg-pair mov
__device__ __forceinline__ u64t bf2_to_f2(unsigned int v) {
    unsigned int lo = v << 16;
    unsigned int hi = v & 0xffff0000u;
    u64t r; asm("mov.b64 %0,{%1,%2};" : "=l"(r) : "r"(lo), "r"(hi)); return r;
}
// two f32 -> bf16x2 (u32); first arg becomes low half
__device__ __forceinline__ unsigned int f2_to_bf2(float lo, float hi) {
    unsigned int r;
    asm("cvt.rn.bf16x2.f32 %0,%1,%2;" : "=r"(r) : "f"(hi), "f"(lo));
    return r;
}

// ---------------- input transform: h = relu(x @ w_in + b_in) ----------------
__global__ void k_input(const float* __restrict__ x, const float* __restrict__ w_in,
                        const float* __restrict__ b_in) {
    __shared__ float ws[F_IN * DD];   // 6 KB
    int tid = threadIdx.x;
    for (int i = tid; i < F_IN * DD; i += 256) ws[i] = w_in[i];
    __syncthreads();
    int j = tid & 63;
    float bj = b_in[j];
#pragma unroll
    for (int rr = 0; rr < 4; rr++) {
        int r = blockIdx.x * 16 + rr * 4 + (tid >> 6);
        if (r < NN) {
            float s = bj;
#pragma unroll
            for (int k = 0; k < F_IN; k++)
                s = fmaf(__ldg(&x[r * F_IN + k]), ws[k * DD + j], s);
            g_h[r * DD + j] = fmaxf(s, 0.f);
        }
    }
}

// ---------------- per-layer transform: xl(bf16) = h@wl+bl, xr(fp32) = h@wr+br ----------------
// Only W staged in smem (32 KB). h rows read directly via __ldg float4
// BROADCASTS (all lanes same address -> 1 L1 wavefront; rows L1-resident,
// reused by all 8 warps). k chunked by 4 -> Hs-side wavefronts cut 4x vs
// scalar broadcasts. Block 0 writes the dummy xl row (index NN): -1e6*att ->
// pad edges score <= -20 for every head => ex2 == ~0.
__global__ void k_transform(const float* __restrict__ wl, const float* __restrict__ bl,
                            const float* __restrict__ wr, const float* __restrict__ br,
                            const float* __restrict__ att) {
    __shared__ float W[DD][2 * DD];   // 32 KB, W[k][j]
    int tid = threadIdx.x;
    int base = blockIdx.x * 64;

    if (blockIdx.x == 0 && tid < 32)
        g_xlb[NN * 32 + tid] = f2_to_bf2(-1e6f * att[2 * tid], -1e6f * att[2 * tid + 1]);

    for (int i = tid; i < DD * 2 * DD; i += 256) {
        int k = i >> 7, j = i & 127;
        W[k][j] = (j < DD) ? wl[k * DD + j] : wr[k * DD + (j - DD)];
    }
    __syncthreads();

    int tx = tid & 31, ty = tid >> 5;
    int c0 = tx * 4;
    float b0, b1, b2, b3;
    if (c0 < DD) { b0 = bl[c0]; b1 = bl[c0 + 1]; b2 = bl[c0 + 2]; b3 = bl[c0 + 3]; }
    else { int c = c0 - DD; b0 = br[c]; b1 = br[c + 1]; b2 = br[c + 2]; b3 = br[c + 3]; }

    u64t acc[8][2];
#pragma unroll
    for (int i = 0; i < 8; i++) { acc[i][0] = pack2(b0, b1); acc[i][1] = pack2(b2, b3); }

    int r0 = base + ty * 8;
    int ro[8];
#pragma unroll
    for (int i = 0; i < 8; i++) ro[i] = min(r0 + i, NN - 1) * DD;

    for (int kc = 0; kc < DD; kc += 4) {
        float4 w0 = *(const float4*)&W[kc][c0];
        float4 w1 = *(const float4*)&W[kc + 1][c0];
        float4 w2 = *(const float4*)&W[kc + 2][c0];
        float4 w3 = *(const float4*)&W[kc + 3][c0];
        u64t wA0 = pack2(w0.x, w0.y), wB0 = pack2(w0.z, w0.w);
        u64t wA1 = pack2(w1.x, w1.y), wB1 = pack2(w1.z, w1.w);
        u64t wA2 = pack2(w2.x, w2.y), wB2 = pack2(w2.z, w2.w);
        u64t wA3 = pack2(w3.x, w3.y), wB3 = pack2(w3.z, w3.w);
#pragma unroll
        for (int i = 0; i < 8; i++) {
            float4 hv = __ldg((const float4*)&g_h[ro[i] + kc]);   // warp-broadcast
            acc[i][0] = fma2(packb(hv.x), wA0, acc[i][0]);
            acc[i][1] = fma2(packb(hv.x), wB0, acc[i][1]);
            acc[i][0] = fma2(packb(hv.y), wA1, acc[i][0]);
            acc[i][1] = fma2(packb(hv.y), wB1, acc[i][1]);
            acc[i][0] = fma2(packb(hv.z), wA2, acc[i][0]);
            acc[i][1] = fma2(packb(hv.z), wB2, acc[i][1]);
            acc[i][0] = fma2(packb(hv.w), wA3, acc[i][0]);
            acc[i][1] = fma2(packb(hv.w), wB3, acc[i][1]);
        }
    }

    if (c0 < DD) {
#pragma unroll
        for (int i = 0; i < 8; i++) {
            int r = base + ty * 8 + i;
            if (r < NN) {
                float2 p0 = unpack2(acc[i][0]), p1 = unpack2(acc[i][1]);
                uint2 o = make_uint2(f2_to_bf2(p0.x, p0.y), f2_to_bf2(p1.x, p1.y));
                *(uint2*)&g_xlb[r * 32 + tx * 2] = o;
            }
        }
    } else {
        int cc = c0 - DD;
#pragma unroll
        for (int i = 0; i < 8; i++) {
            int r = base + ty * 8 + i;
            if (r < NN) {
                float2 p0 = unpack2(acc[i][0]), p1 = unpack2(acc[i][1]);
                *(float4*)&g_xr[r * DD + cc] = make_float4(p0.x, p0.y, p1.x, p1.y);
            }
        }
    }
}

// ---------------- CSR build (padded to multiples of 8 per node) ----------------
__global__ void k_prep() {
    int i = blockIdx.x * blockDim.x + threadIdx.x;
    if (i < NN) g_deg[i] = 0;
    if (i < GG) { g_gstart[i] = NN; g_gend[i] = 0; }
}
__global__ void k_deg(const int* __restrict__ dst) {
    int i = blockIdx.x * blockDim.x + threadIdx.x;
    if (i < EE) atomicAdd(&g_deg[dst[i]], 1);
}
__global__ void k_scan1() {
    __shared__ int sh[SCAN_B];
    int tid = threadIdx.x;
    int i = blockIdx.x * SCAN_B + tid;
    int v = (i < NN) ? ((g_deg[i] + 7) & ~7) : 0;   // padded degree
    sh[tid] = v;
    __syncthreads();
#pragma unroll
    for (int off = 1; off < SCAN_B; off <<= 1) {
        int t = 0;
        if (tid >= off) t = sh[tid - off];
        __syncthreads();
        if (tid >= off) sh[tid] += t;
        __syncthreads();
    }
    if (i < NN) g_excl[i] = sh[tid] - v;
    if (tid == SCAN_B - 1) g_bsum[blockIdx.x] = sh[tid];
}
// block-sum scan fused in (every block redundantly scans the 49 values);
// graph ranges via sorted-batch boundary detection (NO atomics).
__global__ void k_scan3(const int* __restrict__ batch) {
    __shared__ int sb[64];
    int tid = threadIdx.x;
    int v0 = 0;
    if (tid < 64) {
        v0 = (tid < NB) ? g_bsum[tid] : 0;
        sb[tid] = v0;
    }
    __syncthreads();
#pragma unroll
    for (int off = 1; off < 64; off <<= 1) {
        int v = (tid < 64 && tid >= off) ? sb[tid - off] : 0;
        __syncthreads();
        if (tid < 64) sb[tid] += v;
        __syncthreads();
    }
    if (tid < 64) sb[tid] -= v0;   // exclusive
    __syncthreads();

    int i = blockIdx.x * blockDim.x + tid;
    if (i < NN) {
        int v = g_excl[i] + sb[i / SCAN_B];
        g_row[i] = v;
        g_cur[i] = v;
        if (i == NN - 1) g_row[NN] = v + ((g_deg[i] + 7) & ~7);
        // graph ranges: batch is sorted -> boundaries only (no atomics)
        int b = batch[i];
        if (i == 0 || __ldg(&batch[i - 1]) != b) g_gstart[b] = i;
        if (i == NN - 1 || __ldg(&batch[i + 1]) != b) g_gend[b] = i + 1;
    }
}
__global__ void k_fill(const int* __restrict__ src, const int* __restrict__ dst) {
    int i = blockIdx.x * blockDim.x + threadIdx.x;
    if (i < EE) {
        int d = dst[i];
        int pos = atomicAdd(&g_cur[d], 1);
        g_col[pos] = src[i];
    }
}
__global__ void k_padfill() {
    int i = blockIdx.x * blockDim.x + threadIdx.x;
    if (i < NN) {
        int e0 = g_cur[i];         // end of real edges
        int e1 = g_row[i + 1];     // padded end
        for (int j = e0; j < e1; j++) g_col[j] = NN;   // dummy node
    }
}

// ---------------- GATv2 aggregation + residual + LayerNorm (+ReLU / +gate) fused ----------------
// One warp per node; lane owns channels 2*lane,2*lane+1 (f32x2); head = lane>>3.
// xl gathered as bf16x2 (ONE 128B line per edge), kept packed in registers,
// unpacked on the fly (2 ALU ops). Padded CSR (mult of 8): col indices via
// 2x int4, software-pipelined; pads hit the dummy row (weight ~= 0).
// lrelu via 0.6x+0.4|x| with log2e folded into att -> ex2; butterfly
// transpose-reduce (7 SHFL / 8 edges), ONE ex2 per 8 edges per lane.
// DO_GATE instantiation computes the gate MLP in registers.
template <int DO_RELU, int DO_GATE>
__global__ void __launch_bounds__(256) k_agg(
        const float* __restrict__ att, const float* __restrict__ bg,
        const float* __restrict__ lng, const float* __restrict__ lnb,
        const float* __restrict__ w_g1, const float* __restrict__ b_g1,
        const float* __restrict__ w_g2, const float* __restrict__ b_g2) {
    int wid = (blockIdx.x * blockDim.x + threadIdx.x) >> 5;
    int lane = threadIdx.x & 31;
    if (wid >= NN) return;

    const u64t* xru = (const u64t*)g_xr;
    float2* h2 = (float2*)g_h;

    u64t xr = __ldg(&xru[wid * 32 + lane]);
    u64t xls = bf2_to_f2(__ldg(&g_xlb[wid * 32 + lane]));

    const float L2E = 1.4426950408889634f;
    float a0 = __ldg(&att[2 * lane]), a1 = __ldg(&att[2 * lane + 1]);
    u64t a6 = pack2(a0 * (0.6f * L2E), a1 * (0.6f * L2E));
    u64t a4 = pack2(a0 * (0.4f * L2E), a1 * (0.4f * L2E));
    const u64t ABS2 = 0x7FFFFFFF7FFFFFFFull;

    // self loop
    u64t ss = add2(xls, xr);
    u64t pp = fma2(a4, ss & ABS2, mul2(a6, ss));
    float2 qq = unpack2(pp);
    float eself = grp8_sum(qq.x + qq.y);
    float wself = ex2(eself);
    u64t accA = mul2(packb(wself), xls);
    u64t accB = packb(0.f);
    int sub = lane & 7;
    float denom = (sub == 0) ? wself : 0.f;

    int beg = g_row[wid];
    int endp = g_row[wid + 1];   // padded end, multiple of 8
    bool b4 = (lane & 4) != 0, b2 = (lane & 2) != 0, b1 = (lane & 1) != 0;

    if (beg < endp) {
        int4 ca = __ldg((const int4*)&g_col[beg]);
        int4 cb = __ldg((const int4*)&g_col[beg + 4]);
        for (int k = beg; k < endp; k += 8) {
            int cs[8] = { ca.x, ca.y, ca.z, ca.w, cb.x, cb.y, cb.z, cb.w };
            // prefetch next iteration's cols (always-valid address)
            int kn = (k + 8 < endp) ? k + 8 : beg;
            ca = __ldg((const int4*)&g_col[kn]);
            cb = __ldg((const int4*)&g_col[kn + 4]);

            unsigned int vb[8];
#pragma unroll
            for (int j = 0; j < 8; j++) vb[j] = __ldg(&g_xlb[cs[j] * 32 + lane]);
            float ee[8];
#pragma unroll
            for (int j = 0; j < 8; j++) {
                u64t s = add2(bf2_to_f2(vb[j]), xr);
                u64t p = fma2(a4, s & ABS2, mul2(a6, s));
                float2 q = unpack2(p);
                ee[j] = q.x + q.y;
            }
            // butterfly transpose-reduce over the 8-lane head group
            float t0, t1, t2, t3;
            {
                float s0 = b4 ? ee[0] : ee[4];
                float s1 = b4 ? ee[1] : ee[5];
                float s2 = b4 ? ee[2] : ee[6];
                float s3 = b4 ? ee[3] : ee[7];
                t0 = (b4 ? ee[4] : ee[0]) + __shfl_xor_sync(0xffffffffu, s0, 4);
                t1 = (b4 ? ee[5] : ee[1]) + __shfl_xor_sync(0xffffffffu, s1, 4);
                t2 = (b4 ? ee[6] : ee[2]) + __shfl_xor_sync(0xffffffffu, s2, 4);
                t3 = (b4 ? ee[7] : ee[3]) + __shfl_xor_sync(0xffffffffu, s3, 4);
            }
            float u0, u1;
            {
                float s0 = b2 ? t0 : t2;
                float s1 = b2 ? t1 : t3;
                u0 = (b2 ? t2 : t0) + __shfl_xor_sync(0xffffffffu, s0, 2);
                u1 = (b2 ? t3 : t1) + __shfl_xor_sync(0xffffffffu, s1, 2);
            }
            float ef;
            {
                float s0 = b1 ? u0 : u1;
                ef = (b1 ? u1 : u0) + __shfl_xor_sync(0xffffffffu, s0, 1);
            }
            float w = ex2(ef);   // pads: ef <= -20 for every head -> ~0
            denom += w;
#pragma unroll
            for (int j = 0; j < 8; j += 2) {
                float wa = __shfl_sync(0xffffffffu, w, j, 8);
                float wb = __shfl_sync(0xffffffffu, w, j + 1, 8);
                accA = fma2(packb(wa), bf2_to_f2(vb[j]), accA);
                accB = fma2(packb(wb), bf2_to_f2(vb[j + 1]), accB);
            }
        }
    }

    u64t acc = add2(accA, accB);
    denom = grp8_sum(denom);
    float inv_d = 1.f / denom;

    float2 av = unpack2(acc);
    float2 res = h2[wid * 32 + lane];
    float v0 = av.x * inv_d + __ldg(&bg[2 * lane]) + res.x;
    float v1 = av.y * inv_d + __ldg(&bg[2 * lane + 1]) + res.y;

    // LayerNorm over 64 channels (2 per lane)
    float mean = warp_sum(v0 + v1) * (1.f / 64.f);
    float d0 = v0 - mean, d1 = v1 - mean;
    float var = warp_sum(d0 * d0 + d1 * d1) * (1.f / 64.f);
    float inv = rsqrtf(var + LN_EPS);
    float r0 = d0 * inv * __ldg(&lng[2 * lane]) + __ldg(&lnb[2 * lane]);
    float r1 = d1 * inv * __ldg(&lng[2 * lane + 1]) + __ldg(&lnb[2 * lane + 1]);
    if (DO_RELU) { r0 = fmaxf(r0, 0.f); r1 = fmaxf(r1, 0.f); }
    h2[wid * 32 + lane] = make_float2(r0, r1);

    if (DO_GATE) {
        // gate = relu(h @ w_g1 + b_g1) @ w_g2 + b_g2, h already in registers
        float hid = __ldg(&b_g1[lane]);
#pragma unroll
        for (int k = 0; k < DD; k++) {
            float hk = __shfl_sync(0xffffffffu, (k & 1) ? r1 : r0, k >> 1);
            hid = fmaf(hk, __ldg(&w_g1[k * 32 + lane]), hid);
        }
        hid = fmaxf(hid, 0.f);
        float gp = warp_sum(hid * __ldg(&w_g2[lane]));
        if (lane == 0) g_gate[wid] = gp + b_g2[0];
    }
}

// ---------------- global attention pooling per graph + output GEMV ----------------
__global__ void k_pool(const float* __restrict__ w_out, const float* __restrict__ b_out,
                       float* __restrict__ out) {
    __shared__ float red[256];
    __shared__ float accs[4][64];
    __shared__ float gss[4];
    __shared__ float semb[64];
    int g = blockIdx.x, tid = threadIdx.x;
    int s = g_gstart[g], e = g_gend[g];
    float m = -3.4e38f;
    for (int n = s + tid; n < e; n += 256) m = fmaxf(m, g_gate[n]);
    red[tid] = m;
    __syncthreads();
    for (int o = 128; o; o >>= 1) {
        if (tid < o) red[tid] = fmaxf(red[tid], red[tid + o]);
        __syncthreads();
    }
    m = red[0];
    int c = tid & 63, grp = tid >> 6;
    float acc = 0.f, gs = 0.f;
    for (int n = s + grp; n < e; n += 4) {
        float w = __expf(g_gate[n] - m);
        acc = fmaf(w, g_h[n * DD + c], acc);
        if (c == 0) gs += w;
    }
    accs[grp][c] = acc;
    if (c == 0) gss[grp] = gs;
    __syncthreads();
    if (tid < 64) {
        float a = accs[0][tid] + accs[1][tid] + accs[2][tid] + accs[3][tid];
        float gsum = gss[0] + gss[1] + gss[2] + gss[3];
        semb[tid] = a / (gsum > 0.f ? gsum : 1.f);
    }
    __syncthreads();
    if (tid < 64) {
        float sacc = b_out[tid];
#pragma unroll
        for (int k = 0; k < DD; k++) sacc = fmaf(semb[k], w_out[k * DD + tid], sacc);
        out[g * DD + tid] = fmaxf(sacc, 0.f);
    }
}

// ---------------- launch ----------------
extern "C" void kernel_launch(void* const* d_in, const int* in_sizes, int n_in,
                              void* d_out, int out_size) {
    const float* x      = (const float*)d_in[0];
    const int*   ei     = (const int*)d_in[1];
    const int*   batch  = (const int*)d_in[2];
    const float* w_in   = (const float*)d_in[3];
    const float* b_in   = (const float*)d_in[4];
    const float* w_l    = (const float*)d_in[5];
    const float* b_l    = (const float*)d_in[6];
    const float* w_r    = (const float*)d_in[7];
    const float* b_r    = (const float*)d_in[8];
    const float* att    = (const float*)d_in[9];
    const float* b_gat  = (const float*)d_in[10];
    const float* ln_g   = (const float*)d_in[11];
    const float* ln_b   = (const float*)d_in[12];
    const float* w_g1   = (const float*)d_in[13];
    const float* b_g1   = (const float*)d_in[14];
    const float* w_g2   = (const float*)d_in[15];
    const float* b_g2   = (const float*)d_in[16];
    const float* w_out  = (const float*)d_in[17];
    const float* b_out  = (const float*)d_in[18];
    float* out = (float*)d_out;

    const int* src = ei;
    const int* dst = ei + EE;

    // Profiled launch (index 3) = k_transform layer 0.
    k_prep<<<(NN + 255) / 256, 256>>>();
    k_deg<<<(EE + 255) / 256, 256>>>(dst);
    k_input<<<(NN + 15) / 16, 256>>>(x, w_in, b_in);
    k_transform<<<(NN + 63) / 64, 256>>>(w_l, b_l, w_r, b_r, att);   // layer 0

    k_scan1<<<NB, SCAN_B>>>();
    k_scan3<<<(NN + 255) / 256, 256>>>(batch);
    k_fill<<<(EE + 255) / 256, 256>>>(src, dst);
    k_padfill<<<(NN + 255) / 256, 256>>>();

    int agg_grid = (NN * 32 + 255) / 256;

    // layer 0 aggregation
    k_agg<1, 0><<<agg_grid, 256>>>(att, b_gat, ln_g, ln_b, w_g1, b_g1, w_g2, b_g2);

    // layer 1: relu, no gate
    {
        int l = 1;
        k_transform<<<(NN + 63) / 64, 256>>>(w_l + l * DD * DD, b_l + l * DD,
                                             w_r + l * DD * DD, b_r + l * DD,
                                             att + l * DD);
        k_agg<1, 0><<<agg_grid, 256>>>(att + l * DD, b_gat + l * DD,
                                       ln_g + l * DD, ln_b + l * DD,
                                       w_g1, b_g1, w_g2, b_g2);
    }
    // layer 2: no relu, fused gate
    {
        int l = 2;
        k_transform<<<(NN + 63) / 64, 256>>>(w_l + l * DD * DD, b_l + l * DD,
                                             w_r + l * DD * DD, b_r + l * DD,
                                             att + l * DD);
        k_agg<0, 1><<<agg_grid, 256>>>(att + l * DD, b_gat + l * DD,
                                       ln_g + l * DD, ln_b + l * DD,
                                       w_g1, b_g1, w_g2, b_g2);
    }

    // pooling + output
    k_pool<<<GG, 256>>>(w_out, b_out, out);
}

// round 16
// speedup vs baseline: 1.0166x; 1.0166x over previous
#include <cuda_runtime.h>
#include <cuda_bf16.h>
#include <mma.h>

using namespace nvcuda;

#define NN 50000
#define EE 1600000
#define GG 64
#define F_IN 24
#define DD 64
#define HH 4
#define CC 16
#define LL 3
#define NEG 0.2f
#define LN_EPS 1e-5f

#define SCAN_B 1024
#define NB ((NN + SCAN_B - 1) / SCAN_B)   // 49
#define COLCAP (EE + 8 * NN)              // padded CSR capacity (pad to mult of 8)

// ---------------- device scratch (static, no allocation) ----------------
__device__ float g_h[NN * DD];
__device__ float g_xl[(NN + 1) * DD];   // +1 dummy row (index NN) for CSR pads
__device__ float g_xr[NN * DD];
__device__ int   g_deg[NN];
__device__ int   g_excl[NN];
__device__ int   g_row[NN + 1];         // padded offsets; g_row[NN] = total
__device__ int   g_cur[NN];             // fill cursor; after fill = beg+deg
__device__ int   g_col[COLCAP];
__device__ int   g_bsum[NB];
__device__ float g_gate[NN];
__device__ int   g_gstart[GG];
__device__ int   g_gend[GG];

// ---------------- helpers ----------------
__device__ __forceinline__ float grp8_sum(float p) {
    p += __shfl_xor_sync(0xffffffffu, p, 1);
    p += __shfl_xor_sync(0xffffffffu, p, 2);
    p += __shfl_xor_sync(0xffffffffu, p, 4);
    return p;
}
__device__ __forceinline__ float warp_sum(float s) {
#pragma unroll
    for (int o = 16; o; o >>= 1) s += __shfl_xor_sync(0xffffffffu, s, o);
    return s;
}

// ---- packed f32x2 ops (only reachable via PTX on sm_103a) ----
typedef unsigned long long u64t;
__device__ __forceinline__ u64t pack2(float x, float y) {
    u64t r; asm("mov.b64 %0,{%1,%2};" : "=l"(r) : "f"(x), "f"(y)); return r;
}
__device__ __forceinline__ u64t packb(float x) {
    u64t r; asm("mov.b64 %0,{%1,%1};" : "=l"(r) : "f"(x)); return r;
}
__device__ __forceinline__ u64t fma2(u64t a, u64t b, u64t c) {
    u64t d; asm("fma.rn.f32x2 %0,%1,%2,%3;" : "=l"(d) : "l"(a), "l"(b), "l"(c)); return d;
}
__device__ __forceinline__ u64t add2(u64t a, u64t b) {
    u64t d; asm("add.rn.f32x2 %0,%1,%2;" : "=l"(d) : "l"(a), "l"(b)); return d;
}
__device__ __forceinline__ u64t mul2(u64t a, u64t b) {
    u64t d; asm("mul.rn.f32x2 %0,%1,%2;" : "=l"(d) : "l"(a), "l"(b)); return d;
}
__device__ __forceinline__ float2 unpack2(u64t v) {
    float2 f; asm("mov.b64 {%0,%1},%2;" : "=f"(f.x), "=f"(f.y) : "l"(v)); return f;
}
__device__ __forceinline__ float ex2(float x) {
    float y; asm("ex2.approx.f32 %0,%1;" : "=f"(y) : "f"(x)); return y;
}

// ---------------- input transform: h = relu(x @ w_in + b_in) ----------------
__global__ void k_input(const float* __restrict__ x, const float* __restrict__ w_in,
                        const float* __restrict__ b_in) {
    __shared__ float ws[F_IN * DD];   // 6 KB
    int tid = threadIdx.x;
    for (int i = tid; i < F_IN * DD; i += 256) ws[i] = w_in[i];
    __syncthreads();
    int j = tid & 63;
    float bj = b_in[j];
#pragma unroll
    for (int rr = 0; rr < 4; rr++) {
        int r = blockIdx.x * 16 + rr * 4 + (tid >> 6);
        if (r < NN) {
            float s = bj;
#pragma unroll
            for (int k = 0; k < F_IN; k++)
                s = fmaf(__ldg(&x[r * F_IN + k]), ws[k * DD + j], s);
            g_h[r * DD + j] = fmaxf(s, 0.f);
        }
    }
}

// ---------------- per-layer transform via TENSOR CORES (wmma tf32) ----------------
// C[64 x 128] = h[64 x 64] @ [wl | wr][64 x 128] + [bl | br], per block.
// 8 warps: (w & 3) = 16-row tile, (w >> 2) = col half (0 -> xl, 1 -> xr).
// NN % 16 == 0, so each 16-row tile is fully valid or fully skipped.
// Bias preloaded into accumulators from a replicated 16x128 smem tile.
// Block 0 also writes the dummy xl row (index NN): -1e6*att -> pad edges get
// score <= -2e4 for every head => ex2 == 0 exactly.
__global__ void __launch_bounds__(256) k_transform(
        const float* __restrict__ wl, const float* __restrict__ bl,
        const float* __restrict__ wr, const float* __restrict__ br,
        const float* __restrict__ att) {
    __shared__ float Bs[64][128];     // 32 KB: [wl | wr]
    __shared__ float Bias[16][128];   // 8 KB: rows all equal [bl | br]
    int tid = threadIdx.x;
    int base = blockIdx.x * 64;

    if (blockIdx.x == 0 && tid < DD)
        g_xl[NN * DD + tid] = -1e6f * att[tid];

    for (int i = tid; i < 64 * 128; i += 256) {
        int k = i >> 7, j = i & 127;
        Bs[k][j] = (j < DD) ? wl[k * DD + j] : wr[k * DD + (j - DD)];
    }
    for (int i = tid; i < 16 * 128; i += 256) {
        int r = i >> 7, j = i & 127;
        Bias[r][j] = (j < DD) ? bl[j] : br[j - DD];
    }
    __syncthreads();

    int w = tid >> 5;
    int rt = base + (w & 3) * 16;     // 16-row tile base
    if (rt >= NN) return;             // fully invalid tile (after the sync)
    int wc = w >> 2;                  // 0: xl, 1: xr
    float* outp = wc ? g_xr : g_xl;

    wmma::fragment<wmma::accumulator, 16, 16, 8, float> c[4];
#pragma unroll
    for (int t = 0; t < 4; t++)
        wmma::load_matrix_sync(c[t], &Bias[0][wc * 64 + t * 16], 128,
                               wmma::mem_row_major);

    wmma::fragment<wmma::matrix_a, 16, 16, 8, wmma::precision::tf32,
                   wmma::row_major> a;
    wmma::fragment<wmma::matrix_b, 16, 16, 8, wmma::precision::tf32,
                   wmma::row_major> b;

#pragma unroll
    for (int k0 = 0; k0 < DD; k0 += 8) {
        wmma::load_matrix_sync(a, &g_h[rt * DD + k0], DD);
#pragma unroll
        for (int t = 0; t < a.num_elements; t++)
            a.x[t] = wmma::__float_to_tf32(a.x[t]);
#pragma unroll
        for (int t = 0; t < 4; t++) {
            wmma::load_matrix_sync(b, &Bs[k0][wc * 64 + t * 16], 128);
#pragma unroll
            for (int u = 0; u < b.num_elements; u++)
                b.x[u] = wmma::__float_to_tf32(b.x[u]);
            wmma::mma_sync(c[t], a, b, c[t]);
        }
    }

#pragma unroll
    for (int t = 0; t < 4; t++)
        wmma::store_matrix_sync(&outp[rt * DD + t * 16], c[t], DD,
                                wmma::mem_row_major);
}

// ---------------- CSR build (padded to multiples of 8 per node) ----------------
__global__ void k_prep() {
    int i = blockIdx.x * blockDim.x + threadIdx.x;
    if (i < NN) g_deg[i] = 0;
    if (i < GG) { g_gstart[i] = NN; g_gend[i] = 0; }
}
__global__ void k_deg(const int* __restrict__ dst) {
    int i = blockIdx.x * blockDim.x + threadIdx.x;
    if (i < EE) atomicAdd(&g_deg[dst[i]], 1);
}
__global__ void k_scan1() {
    __shared__ int sh[SCAN_B];
    int tid = threadIdx.x;
    int i = blockIdx.x * SCAN_B + tid;
    int v = (i < NN) ? ((g_deg[i] + 7) & ~7) : 0;   // padded degree
    sh[tid] = v;
    __syncthreads();
#pragma unroll
    for (int off = 1; off < SCAN_B; off <<= 1) {
        int t = 0;
        if (tid >= off) t = sh[tid - off];
        __syncthreads();
        if (tid >= off) sh[tid] += t;
        __syncthreads();
    }
    if (i < NN) g_excl[i] = sh[tid] - v;
    if (tid == SCAN_B - 1) g_bsum[blockIdx.x] = sh[tid];
}
// block-sum scan fused in (every block redundantly scans the 49 values);
// graph ranges via sorted-batch boundary detection (NO atomics).
__global__ void k_scan3(const int* __restrict__ batch) {
    __shared__ int sb[64];
    int tid = threadIdx.x;
    int v0 = 0;
    if (tid < 64) {
        v0 = (tid < NB) ? g_bsum[tid] : 0;
        sb[tid] = v0;
    }
    __syncthreads();
#pragma unroll
    for (int off = 1; off < 64; off <<= 1) {
        int v = (tid < 64 && tid >= off) ? sb[tid - off] : 0;
        __syncthreads();
        if (tid < 64) sb[tid] += v;
        __syncthreads();
    }
    if (tid < 64) sb[tid] -= v0;   // exclusive
    __syncthreads();

    int i = blockIdx.x * blockDim.x + tid;
    if (i < NN) {
        int v = g_excl[i] + sb[i / SCAN_B];
        g_row[i] = v;
        g_cur[i] = v;
        if (i == NN - 1) g_row[NN] = v + ((g_deg[i] + 7) & ~7);
        // graph ranges: batch is sorted -> boundaries only (no atomics)
        int b = batch[i];
        if (i == 0 || __ldg(&batch[i - 1]) != b) g_gstart[b] = i;
        if (i == NN - 1 || __ldg(&batch[i + 1]) != b) g_gend[b] = i + 1;
    }
}
__global__ void k_fill(const int* __restrict__ src, const int* __restrict__ dst) {
    int i = blockIdx.x * blockDim.x + threadIdx.x;
    if (i < EE) {
        int d = dst[i];
        int pos = atomicAdd(&g_cur[d], 1);
        g_col[pos] = src[i];
    }
}
__global__ void k_padfill() {
    int i = blockIdx.x * blockDim.x + threadIdx.x;
    if (i < NN) {
        int e0 = g_cur[i];         // end of real edges
        int e1 = g_row[i + 1];     // padded end
        for (int j = e0; j < e1; j++) g_col[j] = NN;   // dummy node
    }
}

// ---------------- GATv2 aggregation + residual + LayerNorm (+ReLU / +gate) fused ----------------
// One warp per node; lane owns channels 2*lane,2*lane+1 (f32x2); head = lane>>3.
// Padded CSR (mult of 8, 32B-aligned): col indices via 2x int4 per iteration,
// software-pipelined (next iteration's cols prefetched during current body),
// no clamps/selects; pads hit the dummy row (weight == 0 exactly).
// lrelu via 0.6x+0.4|x| with log2e folded into att -> ex2; butterfly
// transpose-reduce (7 SHFL / 8 edges), ONE ex2 per 8 edges per lane.
// DO_GATE instantiation (layer 3 only) computes the gate MLP from registers.
template <int DO_RELU, int DO_GATE>
__global__ void __launch_bounds__(256) k_agg(
        const float* __restrict__ att, const float* __restrict__ bg,
        const float* __restrict__ lng, const float* __restrict__ lnb,
        const float* __restrict__ w_g1, const float* __restrict__ b_g1,
        const float* __restrict__ w_g2, const float* __restrict__ b_g2) {
    int wid = (blockIdx.x * blockDim.x + threadIdx.x) >> 5;
    int lane = threadIdx.x & 31;
    if (wid >= NN) return;

    const u64t* xlu = (const u64t*)g_xl;
    const u64t* xru = (const u64t*)g_xr;
    float2* h2 = (float2*)g_h;

    u64t xr = __ldg(&xru[wid * 32 + lane]);
    u64t xls = __ldg(&xlu[wid * 32 + lane]);

    const float L2E = 1.4426950408889634f;
    float a0 = __ldg(&att[2 * lane]), a1 = __ldg(&att[2 * lane + 1]);
    u64t a6 = pack2(a0 * (0.6f * L2E), a1 * (0.6f * L2E));
    u64t a4 = pack2(a0 * (0.4f * L2E), a1 * (0.4f * L2E));
    const u64t ABS2 = 0x7FFFFFFF7FFFFFFFull;

    // self loop
    u64t ss = add2(xls, xr);
    u64t pp = fma2(a4, ss & ABS2, mul2(a6, ss));
    float2 qq = unpack2(pp);
    float eself = grp8_sum(qq.x + qq.y);
    float wself = ex2(eself);
    u64t accA = mul2(packb(wself), xls);
    u64t accB = packb(0.f);
    int sub = lane & 7;
    float denom = (sub == 0) ? wself : 0.f;

    int beg = g_row[wid];
    int endp = g_row[wid + 1];   // padded end, multiple of 8
    bool b4 = (lane & 4) != 0, b2 = (lane & 2) != 0, b1 = (lane & 1) != 0;

    if (beg < endp) {
        int4 ca = __ldg((const int4*)&g_col[beg]);
        int4 cb = __ldg((const int4*)&g_col[beg + 4]);
        for (int k = beg; k < endp; k += 8) {
            int cs[8] = { ca.x, ca.y, ca.z, ca.w, cb.x, cb.y, cb.z, cb.w };
            // prefetch next iteration's cols (always-valid address)
            int kn = (k + 8 < endp) ? k + 8 : beg;
            ca = __ldg((const int4*)&g_col[kn]);
            cb = __ldg((const int4*)&g_col[kn + 4]);

            u64t v[8];
#pragma unroll
            for (int j = 0; j < 8; j++) v[j] = __ldg(&xlu[cs[j] * 32 + lane]);
            float ee[8];
#pragma unroll
            for (int j = 0; j < 8; j++) {
                u64t s = add2(v[j], xr);
                u64t p = fma2(a4, s & ABS2, mul2(a6, s));
                float2 q = unpack2(p);
                ee[j] = q.x + q.y;
            }
            // butterfly transpose-reduce over the 8-lane head group
            float t0, t1, t2, t3;
            {
                float s0 = b4 ? ee[0] : ee[4];
                float s1 = b4 ? ee[1] : ee[5];
                float s2 = b4 ? ee[2] : ee[6];
                float s3 = b4 ? ee[3] : ee[7];
                t0 = (b4 ? ee[4] : ee[0]) + __shfl_xor_sync(0xffffffffu, s0, 4);
                t1 = (b4 ? ee[5] : ee[1]) + __shfl_xor_sync(0xffffffffu, s1, 4);
                t2 = (b4 ? ee[6] : ee[2]) + __shfl_xor_sync(0xffffffffu, s2, 4);
                t3 = (b4 ? ee[7] : ee[3]) + __shfl_xor_sync(0xffffffffu, s3, 4);
            }
            float u0, u1;
            {
                float s0 = b2 ? t0 : t2;
                float s1 = b2 ? t1 : t3;
                u0 = (b2 ? t2 : t0) + __shfl_xor_sync(0xffffffffu, s0, 2);
                u1 = (b2 ? t3 : t1) + __shfl_xor_sync(0xffffffffu, s1, 2);
            }
            float ef;
            {
                float s0 = b1 ? u0 : u1;
                ef = (b1 ? u1 : u0) + __shfl_xor_sync(0xffffffffu, s0, 1);
            }
            float w = ex2(ef);   // pads: ef <= -2e4 -> exactly 0
            denom += w;
#pragma unroll
            for (int j = 0; j < 8; j += 2) {
                float wa = __shfl_sync(0xffffffffu, w, j, 8);
                float wb = __shfl_sync(0xffffffffu, w, j + 1, 8);
                accA = fma2(packb(wa), v[j], accA);
                accB = fma2(packb(wb), v[j + 1], accB);
            }
        }
    }

    u64t acc = add2(accA, accB);
    denom = grp8_sum(denom);
    float inv_d = 1.f / denom;

    float2 av = unpack2(acc);
    float2 res = h2[wid * 32 + lane];
    float v0 = av.x * inv_d + __ldg(&bg[2 * lane]) + res.x;
    float v1 = av.y * inv_d + __ldg(&bg[2 * lane + 1]) + res.y;

    // LayerNorm over 64 channels (2 per lane)
    float mean = warp_sum(v0 + v1) * (1.f / 64.f);
    float d0 = v0 - mean, d1 = v1 - mean;
    float var = warp_sum(d0 * d0 + d1 * d1) * (1.f / 64.f);
    float inv = rsqrtf(var + LN_EPS);
    float r0 = d0 * inv * __ldg(&lng[2 * lane]) + __ldg(&lnb[2 * lane]);
    float r1 = d1 * inv * __ldg(&lng[2 * lane + 1]) + __ldg(&lnb[2 * lane + 1]);
    if (DO_RELU) { r0 = fmaxf(r0, 0.f); r1 = fmaxf(r1, 0.f); }
    h2[wid * 32 + lane] = make_float2(r0, r1);

    if (DO_GATE) {
        // gate = relu(h @ w_g1 + b_g1) @ w_g2 + b_g2, h already in registers
        float hid = __ldg(&b_g1[lane]);
#pragma unroll
        for (int k = 0; k < DD; k++) {
            float hk = __shfl_sync(0xffffffffu, (k & 1) ? r1 : r0, k >> 1);
            hid = fmaf(hk, __ldg(&w_g1[k * 32 + lane]), hid);
        }
        hid = fmaxf(hid, 0.f);
        float gp = warp_sum(hid * __ldg(&w_g2[lane]));
        if (lane == 0) g_gate[wid] = gp + b_g2[0];
    }
}

// ---------------- global attention pooling per graph + output GEMV ----------------
__global__ void k_pool(const float* __restrict__ w_out, const float* __restrict__ b_out,
                       float* __restrict__ out) {
    __shared__ float red[256];
    __shared__ float accs[4][64];
    __shared__ float gss[4];
    __shared__ float semb[64];
    int g = blockIdx.x, tid = threadIdx.x;
    int s = g_gstart[g], e = g_gend[g];
    float m = -3.4e38f;
    for (int n = s + tid; n < e; n += 256) m = fmaxf(m, g_gate[n]);
    red[tid] = m;
    __syncthreads();
    for (int o = 128; o; o >>= 1) {
        if (tid < o) red[tid] = fmaxf(red[tid], red[tid + o]);
        __syncthreads();
    }
    m = red[0];
    int c = tid & 63, grp = tid >> 6;
    float acc = 0.f, gs = 0.f;
    for (int n = s + grp; n < e; n += 4) {
        float w = __expf(g_gate[n] - m);
        acc = fmaf(w, g_h[n * DD + c], acc);
        if (c == 0) gs += w;
    }
    accs[grp][c] = acc;
    if (c == 0) gss[grp] = gs;
    __syncthreads();
    if (tid < 64) {
        float a = accs[0][tid] + accs[1][tid] + accs[2][tid] + accs[3][tid];
        float gsum = gss[0] + gss[1] + gss[2] + gss[3];
        semb[tid] = a / (gsum > 0.f ? gsum : 1.f);
    }
    __syncthreads();
    if (tid < 64) {
        float sacc = b_out[tid];
#pragma unroll
        for (int k = 0; k < DD; k++) sacc = fmaf(semb[k], w_out[k * DD + tid], sacc);
        out[g * DD + tid] = fmaxf(sacc, 0.f);
    }
}

// ---------------- launch ----------------
extern "C" void kernel_launch(void* const* d_in, const int* in_sizes, int n_in,
                              void* d_out, int out_size) {
    const float* x      = (const float*)d_in[0];
    const int*   ei     = (const int*)d_in[1];
    const int*   batch  = (const int*)d_in[2];
    const float* w_in   = (const float*)d_in[3];
    const float* b_in   = (const float*)d_in[4];
    const float* w_l    = (const float*)d_in[5];
    const float* b_l    = (const float*)d_in[6];
    const float* w_r    = (const float*)d_in[7];
    const float* b_r    = (const float*)d_in[8];
    const float* att    = (const float*)d_in[9];
    const float* b_gat  = (const float*)d_in[10];
    const float* ln_g   = (const float*)d_in[11];
    const float* ln_b   = (const float*)d_in[12];
    const float* w_g1   = (const float*)d_in[13];
    const float* b_g1   = (const float*)d_in[14];
    const float* w_g2   = (const float*)d_in[15];
    const float* b_g2   = (const float*)d_in[16];
    const float* w_out  = (const float*)d_in[17];
    const float* b_out  = (const float*)d_in[18];
    float* out = (float*)d_out;

    const int* src = ei;
    const int* dst = ei + EE;

    // Profiled launch (index 3) = k_transform layer 0 (tensor-core path).
    k_prep<<<(NN + 255) / 256, 256>>>();
    k_deg<<<(EE + 255) / 256, 256>>>(dst);
    k_input<<<(NN + 15) / 16, 256>>>(x, w_in, b_in);
    k_transform<<<(NN + 63) / 64, 256>>>(w_l, b_l, w_r, b_r, att);   // layer 0

    k_scan1<<<NB, SCAN_B>>>();
    k_scan3<<<(NN + 255) / 256, 256>>>(batch);
    k_fill<<<(EE + 255) / 256, 256>>>(src, dst);
    k_padfill<<<(NN + 255) / 256, 256>>>();

    int agg_grid = (NN * 32 + 255) / 256;

    // layer 0 aggregation
    k_agg<1, 0><<<agg_grid, 256>>>(att, b_gat, ln_g, ln_b, w_g1, b_g1, w_g2, b_g2);

    // layer 1: relu, no gate
    {
        int l = 1;
        k_transform<<<(NN + 63) / 64, 256>>>(w_l + l * DD * DD, b_l + l * DD,
                                             w_r + l * DD * DD, b_r + l * DD,
                                             att + l * DD);
        k_agg<1, 0><<<agg_grid, 256>>>(att + l * DD, b_gat + l * DD,
                                       ln_g + l * DD, ln_b + l * DD,
                                       w_g1, b_g1, w_g2, b_g2);
    }
    // layer 2: no relu, fused gate
    {
        int l = 2;
        k_transform<<<(NN + 63) / 64, 256>>>(w_l + l * DD * DD, b_l + l * DD,
                                             w_r + l * DD * DD, b_r + l * DD,
                                             att + l * DD);
        k_agg<0, 1><<<agg_grid, 256>>>(att + l * DD, b_gat + l * DD,
                                       ln_g + l * DD, ln_b + l * DD,
                                       w_g1, b_g1, w_g2, b_g2);
    }

    // pooling + output
    k_pool<<<GG, 256>>>(w_out, b_out, out);
}